// round 14
// baseline (speedup 1.0000x reference)
#include <cuda_runtime.h>
#include <cuda_fp16.h>
#include <cstdint>

// DiffusionGraphConv — GB300 sm_103 (baseline PTX; no tcgen05 in this toolchain)
//   1) k_csr: smem histogram + scan (one kernel, 2 CTAs)
//   2) k_scatter_build: edge scatter || X0h build || weight fold (one launch)
//   3) SpMM stage0 + stage1 (software-pipelined gathers: R13 ncu showed
//      latency-bound — issue 42%, L2 60% — NOT a BW wall)
//   4) GEMM all-fp16 MMA: m=0 A hi/lo x2, m>=1 x1

#define NB 4096
#define BB 32
#define DD 64
#define HH 64
#define FF 128
#define EE 65536
#define SS 2
#define MM 5
#define OO 128
#define ROWLEN (BB * FF)

// ---- device scratch ----
__device__ __half g_Xh[(size_t)MM * NB * ROWLEN];      // [X0h,Y0,Z0,Y1,Z1] fp16
__device__ float2 g_edges[SS * EE];
__device__ int    g_off[SS * (NB + 1)];
__device__ int    g_cur[SS * NB];
__device__ __half g_Whf[MM * OO * FF];                 // folded, transposed [m][o][f] fp16

// ---------------- CSR front-end: histogram + scan in one kernel ----------------
__global__ void __launch_bounds__(1024) k_csr(const int* __restrict__ rows) {
    __shared__ int hist[NB];          // 16KB
    __shared__ int wsum[32];
    const int s = blockIdx.x;
    const int t = threadIdx.x;

#pragma unroll
    for (int j = 0; j < 4; j++) hist[t * 4 + j] = 0;
    __syncthreads();

    const int* rp = rows + s * EE;
    for (int i = t; i < EE; i += 1024)
        atomicAdd(&hist[rp[i]], 1);
    __syncthreads();

    int v0 = hist[t * 4 + 0], v1 = hist[t * 4 + 1];
    int v2 = hist[t * 4 + 2], v3 = hist[t * 4 + 3];
    int tot = v0 + v1 + v2 + v3;
    int lane = t & 31, w = t >> 5;
    int x = tot;
#pragma unroll
    for (int d = 1; d < 32; d <<= 1) {
        int y = __shfl_up_sync(0xffffffffu, x, d);
        if (lane >= d) x += y;
    }
    if (lane == 31) wsum[w] = x;
    __syncthreads();
    if (w == 0) {
        int y = wsum[lane];
#pragma unroll
        for (int d = 1; d < 32; d <<= 1) {
            int z = __shfl_up_sync(0xffffffffu, y, d);
            if (lane >= d) y += z;
        }
        wsum[lane] = y;
    }
    __syncthreads();
    int excl = x - tot + (w > 0 ? wsum[w - 1] : 0);
    int ob = s * (NB + 1) + t * 4;
    int cb = s * NB + t * 4;
    g_off[ob + 0] = excl;
    g_off[ob + 1] = excl + v0;
    g_off[ob + 2] = excl + v0 + v1;
    g_off[ob + 3] = excl + v0 + v1 + v2;
    g_cur[cb + 0] = excl;
    g_cur[cb + 1] = excl + v0;
    g_cur[cb + 2] = excl + v0 + v1;
    g_cur[cb + 3] = excl + v0 + v1 + v2;
    if (t == 1023) g_off[s * (NB + 1) + NB] = excl + tot;
}

// ---------------- scatter + X0h build + weight fold (one grid-partitioned launch) ----------------
#define SCAT_BLOCKS ((SS * EE) / 256)                       // 512
#define BUILD_BLOCKS ((NB * BB * 32) / 256)                 // 16384
#define WPREP_BLOCKS ((FF * OO) / 256)                      // 64

__global__ void __launch_bounds__(256) k_scatter_build(
    const int* __restrict__ rows, const int* __restrict__ cols,
    const float* __restrict__ vals,
    const float4* __restrict__ in, const float4* __restrict__ st,
    const float* __restrict__ w) {
    if (blockIdx.x < SCAT_BLOCKS) {
        int i = blockIdx.x * blockDim.x + threadIdx.x;
        int s = i >> 16;
        int r = rows[i];
        int p = atomicAdd(&g_cur[s * NB + r], 1);
        g_edges[s * EE + p] = make_float2(__int_as_float(cols[i]), vals[i]);
    } else if (blockIdx.x < SCAT_BLOCKS + BUILD_BLOCKS) {
        int tid = (blockIdx.x - SCAT_BLOCKS) * blockDim.x + threadIdx.x;
        int q = tid & 31;
        int b = (tid >> 5) & 31;
        int n = tid >> 10;
        float4 v;
        if (q < 16)
            v = in[(size_t)b * (NB * DD / 4) + n * (DD / 4) + q];
        else
            v = st[(size_t)b * (NB * HH / 4) + n * (HH / 4) + (q - 16)];
        size_t off = (size_t)n * ROWLEN + b * FF + q * 4;
        __half2 h0 = __floats2half2_rn(v.x, v.y);
        __half2 h1 = __floats2half2_rn(v.z, v.w);
        uint2 u;
        u.x = *(uint32_t*)&h0;
        u.y = *(uint32_t*)&h1;
        *(uint2*)(g_Xh + off) = u;
    } else {
        int i = (blockIdx.x - SCAT_BLOCKS - BUILD_BLOCKS) * blockDim.x + threadIdx.x;
        int f = i & 127;
        int o = i >> 7;
        float w0 = w[(f * MM + 0) * OO + o];
        float w1 = w[(f * MM + 1) * OO + o];
        float w2 = w[(f * MM + 2) * OO + o];
        float w3 = w[(f * MM + 3) * OO + o];
        float w4 = w[(f * MM + 4) * OO + o];
        float p[5] = {w0 - w2 - w4, w1, 2.f * w2, w3, 2.f * w4};
#pragma unroll
        for (int m = 0; m < MM; m++)
            g_Whf[((size_t)m * OO + o) * FF + f] = __float2half_rn(p[m]);
    }
}

// ---------------- SpMM: smem edges, register-double-buffered gathers ----------------
#define ECHUNK 128

__device__ __forceinline__ void spmm_acc4(__half2* accE, __half2* accO,
                                          const uint2* se, const uint4* r) {
#pragma unroll
    for (int k = 0; k < 4; k++) {
        __half2 vh = *(const __half2*)&se[k].y;
        const __half2* h = (const __half2*)&r[k];
        __half2* acc = (k & 1) ? accO : accE;
#pragma unroll
        for (int j = 0; j < 4; j++)
            acc[j] = __hfma2(vh, h[j], acc[j]);
    }
}

__global__ void __launch_bounds__(256) k_spmm(int stage, int sfix) {
    __shared__ uint2 sedge[ECHUNK];                   // {col, half2(v)}
    const int n = blockIdx.x;
    const int s = (sfix < 0) ? (int)blockIdx.y : sfix;
    const int col = blockIdx.z * 256 + threadIdx.x;   // uint4 index in row [0,512)
    const int srcm = (stage == 0) ? 0 : 1 + 2 * s;
    const int dstm = (stage == 0) ? 1 + 2 * s : 2 + 2 * s;
    const uint4* src = (const uint4*)(g_Xh + (size_t)srcm * NB * ROWLEN) + col;
    uint4* dst = (uint4*)(g_Xh + (size_t)dstm * NB * ROWLEN) + (size_t)n * 512 + col;
    const int e0  = g_off[s * (NB + 1) + n];
    const int end = g_off[s * (NB + 1) + n + 1];
    const float2* ep = g_edges + s * EE;

    __half2 accE[4], accO[4];
    const __half2 z2 = __floats2half2_rn(0.f, 0.f);
#pragma unroll
    for (int j = 0; j < 4; j++) { accE[j] = z2; accO[j] = z2; }

    for (int base = e0; base < end; base += ECHUNK) {
        const int cnt = min(ECHUNK, end - base);
        if (base > e0) __syncthreads();
        if (threadIdx.x < cnt) {
            float2 cv = ep[base + threadIdx.x];
            __half2 vh = __half2half2(__float2half_rn(cv.y));
            sedge[threadIdx.x] = make_uint2((uint32_t)__float_as_int(cv.x),
                                            *(uint32_t*)&vh);
        }
        __syncthreads();

        int i = 0;
        uint2 sa[4], sb[4];
        uint4 ra[4], rb[4];
        int haveA = 0, haveB = 0;
        // prologue: fill both pipeline stages before consuming anything
        if (i + 4 <= cnt) {
#pragma unroll
            for (int k = 0; k < 4; k++) sa[k] = sedge[i + k];
#pragma unroll
            for (int k = 0; k < 4; k++) ra[k] = src[(size_t)sa[k].x * 512];
            i += 4; haveA = 1;
        }
        if (i + 4 <= cnt) {
#pragma unroll
            for (int k = 0; k < 4; k++) sb[k] = sedge[i + k];
#pragma unroll
            for (int k = 0; k < 4; k++) rb[k] = src[(size_t)sb[k].x * 512];
            i += 4; haveB = 1;
        }
        // steady state: consume one stage while the other is in flight
        while (haveA || haveB) {
            if (haveA) {
                spmm_acc4(accE, accO, sa, ra);
                haveA = 0;
                if (i + 4 <= cnt) {
#pragma unroll
                    for (int k = 0; k < 4; k++) sa[k] = sedge[i + k];
#pragma unroll
                    for (int k = 0; k < 4; k++) ra[k] = src[(size_t)sa[k].x * 512];
                    i += 4; haveA = 1;
                }
            }
            if (haveB) {
                spmm_acc4(accE, accO, sb, rb);
                haveB = 0;
                if (i + 4 <= cnt) {
#pragma unroll
                    for (int k = 0; k < 4; k++) sb[k] = sedge[i + k];
#pragma unroll
                    for (int k = 0; k < 4; k++) rb[k] = src[(size_t)sb[k].x * 512];
                    i += 4; haveB = 1;
                }
            }
        }
        // tail (<4 edges)
        for (; i < cnt; i++) {
            uint2 se = sedge[i];
            uint4 r = src[(size_t)se.x * 512];
            __half2 vh = *(__half2*)&se.y;
            const __half2* h = (const __half2*)&r;
#pragma unroll
            for (int j = 0; j < 4; j++)
                accE[j] = __hfma2(vh, h[j], accE[j]);
        }
    }

    uint4 o;
    __half2* po = (__half2*)&o;
#pragma unroll
    for (int j = 0; j < 4; j++) {
        float2 fe = __half22float2(accE[j]);
        float2 fo = __half22float2(accO[j]);
        po[j] = __floats2half2_rn(fe.x + fo.x, fe.y + fo.y);
    }
    *dst = o;
}

// ---------------- GEMM: all fp16 MMA; m=0 A hi/lo x2, m>=1 x1 ----------------
#define BK   32
#define BKP  40
#define TSZ  (128 * BKP)
#define STG3 (3 * TSZ)               // tiles: A(hi) | A(lo) | B
#define GEMM_SMEM (2 * STG3 * 2)     // 61440 B

__device__ __forceinline__ void mma_f16(float* c, const uint32_t* a, const uint32_t* b) {
    asm volatile(
        "mma.sync.aligned.m16n8k16.row.col.f32.f16.f16.f32 "
        "{%0,%1,%2,%3}, {%4,%5,%6,%7}, {%8,%9}, {%0,%1,%2,%3};\n"
        : "+f"(c[0]), "+f"(c[1]), "+f"(c[2]), "+f"(c[3])
        : "r"(a[0]), "r"(a[1]), "r"(a[2]), "r"(a[3]), "r"(b[0]), "r"(b[1]));
}
__device__ __forceinline__ void ldsm_x4(uint32_t* r, uint32_t saddr) {
    asm volatile("ldmatrix.sync.aligned.m8n8.x4.shared.b16 {%0,%1,%2,%3}, [%4];"
                 : "=r"(r[0]), "=r"(r[1]), "=r"(r[2]), "=r"(r[3]) : "r"(saddr));
}

__global__ void __launch_bounds__(256) k_gemm_mma(const float* __restrict__ inputs,
                                                  const float* __restrict__ state,
                                                  const float* __restrict__ biases,
                                                  float* __restrict__ out) {
    extern __shared__ uint16_t smx[];   // [2][Ah|Al|B][128][BKP]
    const uint32_t smem0 = (uint32_t)__cvta_generic_to_shared(smx);

    const int t = threadIdx.x;
    const int wid = t >> 5, lane = t & 31;
    const int qr = lane >> 2, qc = lane & 3;
    const int wm = wid & 1, wn = wid >> 1;

    const int bn0 = blockIdx.x * 128;
    const int n0 = bn0 & (NB - 1);
    const int b  = bn0 >> 12;

    const int ar = t >> 1, ah = t & 1;   // A ldg: row, 16-elem half
    const int bo = t & 127, bp = t >> 7; // B ldg: o row, 16-elem part

    const int aRowOff = (wm * 64 + (lane & 15)) * BKP + ((lane >> 4) << 3);
    const int bRowOff = (wn * 32 + ((lane >> 4) << 3) + (lane & 7)) * BKP + (lane & 8);

    float acc[4][4][4];
#pragma unroll
    for (int i = 0; i < 4; i++)
#pragma unroll
        for (int j = 0; j < 4; j++)
#pragma unroll
            for (int k = 0; k < 4; k++) acc[i][j][k] = 0.f;

    float4 aRegF[4];                 // m=0: fp32 A (from inputs/state)
    uint4  aRegR[2];                 // m>=1: raw fp16 A
    uint4  bReg[2];                  // fp16 W

    auto ldg_tile = [&](int kt) {
        const int m_ = kt >> 2, f0_ = (kt & 3) * BK;
        if (m_ == 0) {
            const int fseg = f0_ + ah * 16;           // {0,16,...,112}
            const float* src = (fseg < DD)
                ? inputs + ((size_t)b * NB + (n0 + ar)) * DD + fseg
                : state  + ((size_t)b * NB + (n0 + ar)) * HH + (fseg - DD);
            const float4* ap = (const float4*)src;
            aRegF[0] = ap[0]; aRegF[1] = ap[1]; aRegF[2] = ap[2]; aRegF[3] = ap[3];
        } else {
            const uint4* apf = (const uint4*)(g_Xh +
                (((size_t)m_ * NB + (n0 + ar)) * BB + b) * FF + f0_ + ah * 16);
            aRegR[0] = apf[0]; aRegR[1] = apf[1];
        }
        const uint4* bf = (const uint4*)(g_Whf + ((size_t)m_ * OO + bo) * FF +
                                         f0_ + bp * 16);
        bReg[0] = bf[0]; bReg[1] = bf[1];
    };

    auto sts_tile = [&](int st, bool isM0) {
        uint16_t* Ah = smx + st * STG3;
        uint16_t* Al = Ah + TSZ;
        uint16_t* Bt = Ah + 2 * TSZ;
        if (isM0) {
            const float* av = (const float*)aRegF;
            uint32_t* AhR = (uint32_t*)(Ah + ar * BKP + ah * 16);
            uint32_t* AlR = (uint32_t*)(Al + ar * BKP + ah * 16);
#pragma unroll
            for (int j = 0; j < 8; j++) {
                float x0 = av[2 * j], x1 = av[2 * j + 1];
                __half h0 = __float2half_rn(x0);
                __half h1 = __float2half_rn(x1);
                __half l0 = __float2half_rn(x0 - __half2float(h0));
                __half l1 = __float2half_rn(x1 - __half2float(h1));
                __half2 hp; hp.x = h0; hp.y = h1;
                __half2 lp; lp.x = l0; lp.y = l1;
                AhR[j] = *(uint32_t*)&hp;
                AlR[j] = *(uint32_t*)&lp;
            }
        } else {
            uint4* Ar = (uint4*)(Ah + ar * BKP + ah * 16);
            Ar[0] = aRegR[0]; Ar[1] = aRegR[1];
        }
        uint4* Br = (uint4*)(Bt + bo * BKP + bp * 16);
        Br[0] = bReg[0]; Br[1] = bReg[1];
    };

    ldg_tile(0);
    sts_tile(0, true);
    __syncthreads();

    for (int kt = 0; kt < 20; kt++) {
        const int st = kt & 1;
        if (kt < 19) ldg_tile(kt + 1);

        const uint32_t baseAh = smem0 + (st * STG3) * 2;
        const uint32_t baseAl = baseAh + TSZ * 2;
        const uint32_t baseB  = baseAh + 2 * TSZ * 2;

        if (kt < 4) {
            // m=0 slab: fp16 hi/lo x2
#pragma unroll
            for (int kk = 0; kk < BK; kk += 16) {
                uint32_t fb[4][2];
#pragma unroll
                for (int p = 0; p < 2; p++) {
                    uint32_t r[4];
                    uint32_t off = (bRowOff + p * 16 * BKP + kk) * 2;
                    ldsm_x4(r, baseB + off);
                    fb[2 * p][0] = r[0]; fb[2 * p][1] = r[1];
                    fb[2 * p + 1][0] = r[2]; fb[2 * p + 1][1] = r[3];
                }
#pragma unroll
                for (int mi = 0; mi < 4; mi++) {
                    uint32_t fah[4], fal[4];
                    uint32_t off = (aRowOff + mi * 16 * BKP + kk) * 2;
                    ldsm_x4(fah, baseAh + off);
                    ldsm_x4(fal, baseAl + off);
#pragma unroll
                    for (int ni = 0; ni < 4; ni++) {
                        mma_f16(acc[mi][ni], fah, fb[ni]);
                        mma_f16(acc[mi][ni], fal, fb[ni]);
                    }
                }
            }
        } else {
            // m>=1 slabs: single fp16 MMA
#pragma unroll
            for (int kk = 0; kk < BK; kk += 16) {
                uint32_t fb[4][2];
#pragma unroll
                for (int p = 0; p < 2; p++) {
                    uint32_t r[4];
                    uint32_t off = (bRowOff + p * 16 * BKP + kk) * 2;
                    ldsm_x4(r, baseB + off);
                    fb[2 * p][0] = r[0]; fb[2 * p][1] = r[1];
                    fb[2 * p + 1][0] = r[2]; fb[2 * p + 1][1] = r[3];
                }
#pragma unroll
                for (int mi = 0; mi < 4; mi++) {
                    uint32_t fa[4];
                    uint32_t off = (aRowOff + mi * 16 * BKP + kk) * 2;
                    ldsm_x4(fa, baseAh + off);
#pragma unroll
                    for (int ni = 0; ni < 4; ni++)
                        mma_f16(acc[mi][ni], fa, fb[ni]);
                }
            }
        }

        if (kt < 19) sts_tile(1 - st, (kt + 1) < 4);
        __syncthreads();
    }

#pragma unroll
    for (int mi = 0; mi < 4; mi++) {
#pragma unroll
        for (int ni = 0; ni < 4; ni++) {
            int col = wn * 32 + ni * 8 + 2 * qc;
            float b0 = biases[col], b1 = biases[col + 1];
            int r0 = bn0 + wm * 64 + mi * 16 + qr;
            float2 v0 = make_float2(acc[mi][ni][0] + b0, acc[mi][ni][1] + b1);
            float2 v1 = make_float2(acc[mi][ni][2] + b0, acc[mi][ni][3] + b1);
            *(float2*)(out + (size_t)r0 * OO + col)       = v0;
            *(float2*)(out + (size_t)(r0 + 8) * OO + col) = v1;
        }
    }
}

// ---------------- launch (serial, 5 launches) ----------------
extern "C" void kernel_launch(void* const* d_in, const int* in_sizes, int n_in,
                              void* d_out, int out_size) {
    const float* inputs = (const float*)d_in[0];
    const float* state  = (const float*)d_in[1];
    const int*   rows   = (const int*)d_in[2];
    const int*   cols   = (const int*)d_in[3];
    const float* vals   = (const float*)d_in[4];
    const float* weight = (const float*)d_in[5];
    const float* biases = (const float*)d_in[6];
    float* out = (float*)d_out;
    (void)in_sizes; (void)n_in; (void)out_size;

    cudaFuncSetAttribute(k_gemm_mma, cudaFuncAttributeMaxDynamicSharedMemorySize,
                         GEMM_SMEM);

    k_csr<<<SS, 1024>>>(rows);
    k_scatter_build<<<SCAT_BLOCKS + BUILD_BLOCKS + WPREP_BLOCKS, 256>>>(
        rows, cols, vals, (const float4*)inputs, (const float4*)state, weight);
    k_spmm<<<dim3(NB, SS, 2), 256>>>(0, -1);   // stage0: both supports (shared src)
    k_spmm<<<dim3(NB, 1, 2), 256>>>(1, 0);     // stage1 s=0
    k_spmm<<<dim3(NB, 1, 2), 256>>>(1, 1);     // stage1 s=1
    k_gemm_mma<<<(BB * NB) / 128, 256, GEMM_SMEM>>>(inputs, state, biases, out);
}

// round 15
// speedup vs baseline: 1.1365x; 1.1365x over previous
#include <cuda_runtime.h>
#include <cuda_fp16.h>
#include <cstdint>

// DiffusionGraphConv — GB300 sm_103 (baseline PTX; no tcgen05 in this toolchain)
//   1) k_csr: smem histogram + scan (one kernel, 2 CTAs)
//   2) k_scatter_build: edge scatter || X0h build || weight fold (one launch)
//   3) SpMM persistent grid-stride (R14's reg-heavy pipeline reverted: occupancy
//      is the latency-hiding mechanism, 39 regs / 66% occ beats 78 regs / 34%)
//   4) GEMM all-fp16 MMA: m=0 A hi/lo x2, m>=1 x1

#define NB 4096
#define BB 32
#define DD 64
#define HH 64
#define FF 128
#define EE 65536
#define SS 2
#define MM 5
#define OO 128
#define ROWLEN (BB * FF)

// ---- device scratch ----
__device__ __half g_Xh[(size_t)MM * NB * ROWLEN];      // [X0h,Y0,Z0,Y1,Z1] fp16
__device__ float2 g_edges[SS * EE];
__device__ int    g_off[SS * (NB + 1)];
__device__ int    g_cur[SS * NB];
__device__ __half g_Whf[MM * OO * FF];                 // folded, transposed [m][o][f] fp16

// ---------------- CSR front-end: histogram + scan in one kernel ----------------
__global__ void __launch_bounds__(1024) k_csr(const int* __restrict__ rows) {
    __shared__ int hist[NB];          // 16KB
    __shared__ int wsum[32];
    const int s = blockIdx.x;
    const int t = threadIdx.x;

#pragma unroll
    for (int j = 0; j < 4; j++) hist[t * 4 + j] = 0;
    __syncthreads();

    const int* rp = rows + s * EE;
    for (int i = t; i < EE; i += 1024)
        atomicAdd(&hist[rp[i]], 1);
    __syncthreads();

    int v0 = hist[t * 4 + 0], v1 = hist[t * 4 + 1];
    int v2 = hist[t * 4 + 2], v3 = hist[t * 4 + 3];
    int tot = v0 + v1 + v2 + v3;
    int lane = t & 31, w = t >> 5;
    int x = tot;
#pragma unroll
    for (int d = 1; d < 32; d <<= 1) {
        int y = __shfl_up_sync(0xffffffffu, x, d);
        if (lane >= d) x += y;
    }
    if (lane == 31) wsum[w] = x;
    __syncthreads();
    if (w == 0) {
        int y = wsum[lane];
#pragma unroll
        for (int d = 1; d < 32; d <<= 1) {
            int z = __shfl_up_sync(0xffffffffu, y, d);
            if (lane >= d) y += z;
        }
        wsum[lane] = y;
    }
    __syncthreads();
    int excl = x - tot + (w > 0 ? wsum[w - 1] : 0);
    int ob = s * (NB + 1) + t * 4;
    int cb = s * NB + t * 4;
    g_off[ob + 0] = excl;
    g_off[ob + 1] = excl + v0;
    g_off[ob + 2] = excl + v0 + v1;
    g_off[ob + 3] = excl + v0 + v1 + v2;
    g_cur[cb + 0] = excl;
    g_cur[cb + 1] = excl + v0;
    g_cur[cb + 2] = excl + v0 + v1;
    g_cur[cb + 3] = excl + v0 + v1 + v2;
    if (t == 1023) g_off[s * (NB + 1) + NB] = excl + tot;
}

// ---------------- scatter + X0h build + weight fold (one grid-partitioned launch) ----------------
#define SCAT_BLOCKS ((SS * EE) / 256)                       // 512
#define BUILD_BLOCKS ((NB * BB * 32) / 256)                 // 16384
#define WPREP_BLOCKS ((FF * OO) / 256)                      // 64

__global__ void __launch_bounds__(256) k_scatter_build(
    const int* __restrict__ rows, const int* __restrict__ cols,
    const float* __restrict__ vals,
    const float4* __restrict__ in, const float4* __restrict__ st,
    const float* __restrict__ w) {
    if (blockIdx.x < SCAT_BLOCKS) {
        int i = blockIdx.x * blockDim.x + threadIdx.x;
        int s = i >> 16;
        int r = rows[i];
        int p = atomicAdd(&g_cur[s * NB + r], 1);
        g_edges[s * EE + p] = make_float2(__int_as_float(cols[i]), vals[i]);
    } else if (blockIdx.x < SCAT_BLOCKS + BUILD_BLOCKS) {
        int tid = (blockIdx.x - SCAT_BLOCKS) * blockDim.x + threadIdx.x;
        int q = tid & 31;
        int b = (tid >> 5) & 31;
        int n = tid >> 10;
        float4 v;
        if (q < 16)
            v = in[(size_t)b * (NB * DD / 4) + n * (DD / 4) + q];
        else
            v = st[(size_t)b * (NB * HH / 4) + n * (HH / 4) + (q - 16)];
        size_t off = (size_t)n * ROWLEN + b * FF + q * 4;
        __half2 h0 = __floats2half2_rn(v.x, v.y);
        __half2 h1 = __floats2half2_rn(v.z, v.w);
        uint2 u;
        u.x = *(uint32_t*)&h0;
        u.y = *(uint32_t*)&h1;
        *(uint2*)(g_Xh + off) = u;
    } else {
        int i = (blockIdx.x - SCAT_BLOCKS - BUILD_BLOCKS) * blockDim.x + threadIdx.x;
        int f = i & 127;
        int o = i >> 7;
        float w0 = w[(f * MM + 0) * OO + o];
        float w1 = w[(f * MM + 1) * OO + o];
        float w2 = w[(f * MM + 2) * OO + o];
        float w3 = w[(f * MM + 3) * OO + o];
        float w4 = w[(f * MM + 4) * OO + o];
        float p[5] = {w0 - w2 - w4, w1, 2.f * w2, w3, 2.f * w4};
#pragma unroll
        for (int m = 0; m < MM; m++)
            g_Whf[((size_t)m * OO + o) * FF + f] = __float2half_rn(p[m]);
    }
}

// ---------------- SpMM: persistent grid-stride over (n,s,z) items ----------------
#define ECHUNK 128
#define SPMM_GRID 2048
#define SPMM_ITEMS (NB * SS * 2)     // 16384

__global__ void __launch_bounds__(256) k_spmm(int stage) {
    __shared__ uint2 sedge[ECHUNK];                   // {col, half2(v)}
    const int t = threadIdx.x;

    for (int item = blockIdx.x; item < SPMM_ITEMS; item += SPMM_GRID) {
        const int n = item >> 2;
        const int s = (item >> 1) & 1;
        const int z = item & 1;
        const int col = z * 256 + t;                  // uint4 index in row [0,512)
        const int srcm = (stage == 0) ? 0 : 1 + 2 * s;
        const int dstm = (stage == 0) ? 1 + 2 * s : 2 + 2 * s;
        const uint4* src = (const uint4*)(g_Xh + (size_t)srcm * NB * ROWLEN) + col;
        uint4* dst = (uint4*)(g_Xh + (size_t)dstm * NB * ROWLEN) +
                     (size_t)n * 512 + col;
        const int e0  = g_off[s * (NB + 1) + n];
        const int end = g_off[s * (NB + 1) + n + 1];
        const float2* ep = g_edges + s * EE;

        __half2 accE[4], accO[4];
        const __half2 z2 = __floats2half2_rn(0.f, 0.f);
#pragma unroll
        for (int j = 0; j < 4; j++) { accE[j] = z2; accO[j] = z2; }

        for (int base = e0; base < end; base += ECHUNK) {
            const int cnt = min(ECHUNK, end - base);
            __syncthreads();                          // sedge reuse across chunks/items
            if (t < cnt) {
                float2 cv = ep[base + t];
                __half2 vh = __half2half2(__float2half_rn(cv.y));
                sedge[t] = make_uint2((uint32_t)__float_as_int(cv.x),
                                      *(uint32_t*)&vh);
            }
            __syncthreads();

            int i = 0;
            for (; i + 8 <= cnt; i += 8) {
                uint2 se[8];
#pragma unroll
                for (int k = 0; k < 8; k++) se[k] = sedge[i + k];
                uint4 r[8];
#pragma unroll
                for (int k = 0; k < 8; k++)
                    r[k] = src[(size_t)se[k].x * 512];
#pragma unroll
                for (int k = 0; k < 8; k++) {
                    __half2 vh = *(__half2*)&se[k].y;
                    const __half2* h = (const __half2*)&r[k];
                    __half2* acc = (k & 1) ? accO : accE;
#pragma unroll
                    for (int j = 0; j < 4; j++)
                        acc[j] = __hfma2(vh, h[j], acc[j]);
                }
            }
            for (; i < cnt; i++) {
                uint2 se = sedge[i];
                uint4 r = src[(size_t)se.x * 512];
                __half2 vh = *(__half2*)&se.y;
                const __half2* h = (const __half2*)&r;
#pragma unroll
                for (int j = 0; j < 4; j++)
                    accE[j] = __hfma2(vh, h[j], accE[j]);
            }
        }

        uint4 o;
        __half2* po = (__half2*)&o;
#pragma unroll
        for (int j = 0; j < 4; j++) {
            float2 fe = __half22float2(accE[j]);
            float2 fo = __half22float2(accO[j]);
            po[j] = __floats2half2_rn(fe.x + fo.x, fe.y + fo.y);
        }
        *dst = o;
    }
}

// ---------------- GEMM: all fp16 MMA; m=0 A hi/lo x2, m>=1 x1 ----------------
#define BK   32
#define BKP  40
#define TSZ  (128 * BKP)
#define STG3 (3 * TSZ)               // tiles: A(hi) | A(lo) | B
#define GEMM_SMEM (2 * STG3 * 2)     // 61440 B

__device__ __forceinline__ void mma_f16(float* c, const uint32_t* a, const uint32_t* b) {
    asm volatile(
        "mma.sync.aligned.m16n8k16.row.col.f32.f16.f16.f32 "
        "{%0,%1,%2,%3}, {%4,%5,%6,%7}, {%8,%9}, {%0,%1,%2,%3};\n"
        : "+f"(c[0]), "+f"(c[1]), "+f"(c[2]), "+f"(c[3])
        : "r"(a[0]), "r"(a[1]), "r"(a[2]), "r"(a[3]), "r"(b[0]), "r"(b[1]));
}
__device__ __forceinline__ void ldsm_x4(uint32_t* r, uint32_t saddr) {
    asm volatile("ldmatrix.sync.aligned.m8n8.x4.shared.b16 {%0,%1,%2,%3}, [%4];"
                 : "=r"(r[0]), "=r"(r[1]), "=r"(r[2]), "=r"(r[3]) : "r"(saddr));
}

__global__ void __launch_bounds__(256) k_gemm_mma(const float* __restrict__ inputs,
                                                  const float* __restrict__ state,
                                                  const float* __restrict__ biases,
                                                  float* __restrict__ out) {
    extern __shared__ uint16_t smx[];   // [2][Ah|Al|B][128][BKP]
    const uint32_t smem0 = (uint32_t)__cvta_generic_to_shared(smx);

    const int t = threadIdx.x;
    const int wid = t >> 5, lane = t & 31;
    const int qr = lane >> 2, qc = lane & 3;
    const int wm = wid & 1, wn = wid >> 1;

    const int bn0 = blockIdx.x * 128;
    const int n0 = bn0 & (NB - 1);
    const int b  = bn0 >> 12;

    const int ar = t >> 1, ah = t & 1;   // A ldg: row, 16-elem half
    const int bo = t & 127, bp = t >> 7; // B ldg: o row, 16-elem part

    const int aRowOff = (wm * 64 + (lane & 15)) * BKP + ((lane >> 4) << 3);
    const int bRowOff = (wn * 32 + ((lane >> 4) << 3) + (lane & 7)) * BKP + (lane & 8);

    float acc[4][4][4];
#pragma unroll
    for (int i = 0; i < 4; i++)
#pragma unroll
        for (int j = 0; j < 4; j++)
#pragma unroll
            for (int k = 0; k < 4; k++) acc[i][j][k] = 0.f;

    float4 aRegF[4];                 // m=0: fp32 A (from inputs/state)
    uint4  aRegR[2];                 // m>=1: raw fp16 A
    uint4  bReg[2];                  // fp16 W

    auto ldg_tile = [&](int kt) {
        const int m_ = kt >> 2, f0_ = (kt & 3) * BK;
        if (m_ == 0) {
            const int fseg = f0_ + ah * 16;           // {0,16,...,112}
            const float* src = (fseg < DD)
                ? inputs + ((size_t)b * NB + (n0 + ar)) * DD + fseg
                : state  + ((size_t)b * NB + (n0 + ar)) * HH + (fseg - DD);
            const float4* ap = (const float4*)src;
            aRegF[0] = ap[0]; aRegF[1] = ap[1]; aRegF[2] = ap[2]; aRegF[3] = ap[3];
        } else {
            const uint4* apf = (const uint4*)(g_Xh +
                (((size_t)m_ * NB + (n0 + ar)) * BB + b) * FF + f0_ + ah * 16);
            aRegR[0] = apf[0]; aRegR[1] = apf[1];
        }
        const uint4* bf = (const uint4*)(g_Whf + ((size_t)m_ * OO + bo) * FF +
                                         f0_ + bp * 16);
        bReg[0] = bf[0]; bReg[1] = bf[1];
    };

    auto sts_tile = [&](int st, bool isM0) {
        uint16_t* Ah = smx + st * STG3;
        uint16_t* Al = Ah + TSZ;
        uint16_t* Bt = Ah + 2 * TSZ;
        if (isM0) {
            const float* av = (const float*)aRegF;
            uint32_t* AhR = (uint32_t*)(Ah + ar * BKP + ah * 16);
            uint32_t* AlR = (uint32_t*)(Al + ar * BKP + ah * 16);
#pragma unroll
            for (int j = 0; j < 8; j++) {
                float x0 = av[2 * j], x1 = av[2 * j + 1];
                __half h0 = __float2half_rn(x0);
                __half h1 = __float2half_rn(x1);
                __half l0 = __float2half_rn(x0 - __half2float(h0));
                __half l1 = __float2half_rn(x1 - __half2float(h1));
                __half2 hp; hp.x = h0; hp.y = h1;
                __half2 lp; lp.x = l0; lp.y = l1;
                AhR[j] = *(uint32_t*)&hp;
                AlR[j] = *(uint32_t*)&lp;
            }
        } else {
            uint4* Ar = (uint4*)(Ah + ar * BKP + ah * 16);
            Ar[0] = aRegR[0]; Ar[1] = aRegR[1];
        }
        uint4* Br = (uint4*)(Bt + bo * BKP + bp * 16);
        Br[0] = bReg[0]; Br[1] = bReg[1];
    };

    ldg_tile(0);
    sts_tile(0, true);
    __syncthreads();

    for (int kt = 0; kt < 20; kt++) {
        const int st = kt & 1;
        if (kt < 19) ldg_tile(kt + 1);

        const uint32_t baseAh = smem0 + (st * STG3) * 2;
        const uint32_t baseAl = baseAh + TSZ * 2;
        const uint32_t baseB  = baseAh + 2 * TSZ * 2;

        if (kt < 4) {
            // m=0 slab: fp16 hi/lo x2
#pragma unroll
            for (int kk = 0; kk < BK; kk += 16) {
                uint32_t fb[4][2];
#pragma unroll
                for (int p = 0; p < 2; p++) {
                    uint32_t r[4];
                    uint32_t off = (bRowOff + p * 16 * BKP + kk) * 2;
                    ldsm_x4(r, baseB + off);
                    fb[2 * p][0] = r[0]; fb[2 * p][1] = r[1];
                    fb[2 * p + 1][0] = r[2]; fb[2 * p + 1][1] = r[3];
                }
#pragma unroll
                for (int mi = 0; mi < 4; mi++) {
                    uint32_t fah[4], fal[4];
                    uint32_t off = (aRowOff + mi * 16 * BKP + kk) * 2;
                    ldsm_x4(fah, baseAh + off);
                    ldsm_x4(fal, baseAl + off);
#pragma unroll
                    for (int ni = 0; ni < 4; ni++) {
                        mma_f16(acc[mi][ni], fah, fb[ni]);
                        mma_f16(acc[mi][ni], fal, fb[ni]);
                    }
                }
            }
        } else {
            // m>=1 slabs: single fp16 MMA
#pragma unroll
            for (int kk = 0; kk < BK; kk += 16) {
                uint32_t fb[4][2];
#pragma unroll
                for (int p = 0; p < 2; p++) {
                    uint32_t r[4];
                    uint32_t off = (bRowOff + p * 16 * BKP + kk) * 2;
                    ldsm_x4(r, baseB + off);
                    fb[2 * p][0] = r[0]; fb[2 * p][1] = r[1];
                    fb[2 * p + 1][0] = r[2]; fb[2 * p + 1][1] = r[3];
                }
#pragma unroll
                for (int mi = 0; mi < 4; mi++) {
                    uint32_t fa[4];
                    uint32_t off = (aRowOff + mi * 16 * BKP + kk) * 2;
                    ldsm_x4(fa, baseAh + off);
#pragma unroll
                    for (int ni = 0; ni < 4; ni++)
                        mma_f16(acc[mi][ni], fa, fb[ni]);
                }
            }
        }

        if (kt < 19) sts_tile(1 - st, (kt + 1) < 4);
        __syncthreads();
    }

#pragma unroll
    for (int mi = 0; mi < 4; mi++) {
#pragma unroll
        for (int ni = 0; ni < 4; ni++) {
            int col = wn * 32 + ni * 8 + 2 * qc;
            float b0 = biases[col], b1 = biases[col + 1];
            int r0 = bn0 + wm * 64 + mi * 16 + qr;
            float2 v0 = make_float2(acc[mi][ni][0] + b0, acc[mi][ni][1] + b1);
            float2 v1 = make_float2(acc[mi][ni][2] + b0, acc[mi][ni][3] + b1);
            *(float2*)(out + (size_t)r0 * OO + col)       = v0;
            *(float2*)(out + (size_t)(r0 + 8) * OO + col) = v1;
        }
    }
}

// ---------------- launch (serial, 5 launches) ----------------
extern "C" void kernel_launch(void* const* d_in, const int* in_sizes, int n_in,
                              void* d_out, int out_size) {
    const float* inputs = (const float*)d_in[0];
    const float* state  = (const float*)d_in[1];
    const int*   rows   = (const int*)d_in[2];
    const int*   cols   = (const int*)d_in[3];
    const float* vals   = (const float*)d_in[4];
    const float* weight = (const float*)d_in[5];
    const float* biases = (const float*)d_in[6];
    float* out = (float*)d_out;
    (void)in_sizes; (void)n_in; (void)out_size;

    cudaFuncSetAttribute(k_gemm_mma, cudaFuncAttributeMaxDynamicSharedMemorySize,
                         GEMM_SMEM);

    k_csr<<<SS, 1024>>>(rows);
    k_scatter_build<<<SCAT_BLOCKS + BUILD_BLOCKS + WPREP_BLOCKS, 256>>>(
        rows, cols, vals, (const float4*)inputs, (const float4*)state, weight);
    k_spmm<<<SPMM_GRID, 256>>>(0);
    k_spmm<<<SPMM_GRID, 256>>>(1);
    k_gemm_mma<<<(BB * NB) / 128, 256, GEMM_SMEM>>>(inputs, state, biases, out);
}

// round 16
// speedup vs baseline: 1.1806x; 1.0388x over previous
#include <cuda_runtime.h>
#include <cuda_fp16.h>
#include <cstdint>

// DiffusionGraphConv — GB300 sm_103 (baseline PTX; no tcgen05 in this toolchain)
//   1) k_csr: smem histogram + scan (one kernel, 2 CTAs)
//   2) k_scatter_build: edge scatter || X0h build || weight fold (one launch)
//   3) SpMM: 4 symmetric per-support launches (R15 showed launch-order locality
//      keeps the gather in L2 — persistent/grid-stride spilled to DRAM)
//   4) GEMM all-fp16 MMA: m=0 A hi/lo x2, m>=1 x1

#define NB 4096
#define BB 32
#define DD 64
#define HH 64
#define FF 128
#define EE 65536
#define SS 2
#define MM 5
#define OO 128
#define ROWLEN (BB * FF)

// ---- device scratch ----
__device__ __half g_Xh[(size_t)MM * NB * ROWLEN];      // [X0h,Y0,Z0,Y1,Z1] fp16
__device__ float2 g_edges[SS * EE];
__device__ int    g_off[SS * (NB + 1)];
__device__ int    g_cur[SS * NB];
__device__ __half g_Whf[MM * OO * FF];                 // folded, transposed [m][o][f] fp16

// ---------------- CSR front-end: histogram + scan in one kernel ----------------
__global__ void __launch_bounds__(1024) k_csr(const int* __restrict__ rows) {
    __shared__ int hist[NB];          // 16KB
    __shared__ int wsum[32];
    const int s = blockIdx.x;
    const int t = threadIdx.x;

#pragma unroll
    for (int j = 0; j < 4; j++) hist[t * 4 + j] = 0;
    __syncthreads();

    const int* rp = rows + s * EE;
    for (int i = t; i < EE; i += 1024)
        atomicAdd(&hist[rp[i]], 1);
    __syncthreads();

    int v0 = hist[t * 4 + 0], v1 = hist[t * 4 + 1];
    int v2 = hist[t * 4 + 2], v3 = hist[t * 4 + 3];
    int tot = v0 + v1 + v2 + v3;
    int lane = t & 31, w = t >> 5;
    int x = tot;
#pragma unroll
    for (int d = 1; d < 32; d <<= 1) {
        int y = __shfl_up_sync(0xffffffffu, x, d);
        if (lane >= d) x += y;
    }
    if (lane == 31) wsum[w] = x;
    __syncthreads();
    if (w == 0) {
        int y = wsum[lane];
#pragma unroll
        for (int d = 1; d < 32; d <<= 1) {
            int z = __shfl_up_sync(0xffffffffu, y, d);
            if (lane >= d) y += z;
        }
        wsum[lane] = y;
    }
    __syncthreads();
    int excl = x - tot + (w > 0 ? wsum[w - 1] : 0);
    int ob = s * (NB + 1) + t * 4;
    int cb = s * NB + t * 4;
    g_off[ob + 0] = excl;
    g_off[ob + 1] = excl + v0;
    g_off[ob + 2] = excl + v0 + v1;
    g_off[ob + 3] = excl + v0 + v1 + v2;
    g_cur[cb + 0] = excl;
    g_cur[cb + 1] = excl + v0;
    g_cur[cb + 2] = excl + v0 + v1;
    g_cur[cb + 3] = excl + v0 + v1 + v2;
    if (t == 1023) g_off[s * (NB + 1) + NB] = excl + tot;
}

// ---------------- scatter + X0h build + weight fold (one grid-partitioned launch) ----------------
#define SCAT_BLOCKS ((SS * EE) / 256)                       // 512
#define BUILD_BLOCKS ((NB * BB * 32) / 256)                 // 16384
#define WPREP_BLOCKS ((FF * OO) / 256)                      // 64

__global__ void __launch_bounds__(256) k_scatter_build(
    const int* __restrict__ rows, const int* __restrict__ cols,
    const float* __restrict__ vals,
    const float4* __restrict__ in, const float4* __restrict__ st,
    const float* __restrict__ w) {
    if (blockIdx.x < SCAT_BLOCKS) {
        int i = blockIdx.x * blockDim.x + threadIdx.x;
        int s = i >> 16;
        int r = rows[i];
        int p = atomicAdd(&g_cur[s * NB + r], 1);
        g_edges[s * EE + p] = make_float2(__int_as_float(cols[i]), vals[i]);
    } else if (blockIdx.x < SCAT_BLOCKS + BUILD_BLOCKS) {
        int tid = (blockIdx.x - SCAT_BLOCKS) * blockDim.x + threadIdx.x;
        int q = tid & 31;
        int b = (tid >> 5) & 31;
        int n = tid >> 10;
        float4 v;
        if (q < 16)
            v = in[(size_t)b * (NB * DD / 4) + n * (DD / 4) + q];
        else
            v = st[(size_t)b * (NB * HH / 4) + n * (HH / 4) + (q - 16)];
        size_t off = (size_t)n * ROWLEN + b * FF + q * 4;
        __half2 h0 = __floats2half2_rn(v.x, v.y);
        __half2 h1 = __floats2half2_rn(v.z, v.w);
        uint2 u;
        u.x = *(uint32_t*)&h0;
        u.y = *(uint32_t*)&h1;
        *(uint2*)(g_Xh + off) = u;
    } else {
        int i = (blockIdx.x - SCAT_BLOCKS - BUILD_BLOCKS) * blockDim.x + threadIdx.x;
        int f = i & 127;
        int o = i >> 7;
        float w0 = w[(f * MM + 0) * OO + o];
        float w1 = w[(f * MM + 1) * OO + o];
        float w2 = w[(f * MM + 2) * OO + o];
        float w3 = w[(f * MM + 3) * OO + o];
        float w4 = w[(f * MM + 4) * OO + o];
        float p[5] = {w0 - w2 - w4, w1, 2.f * w2, w3, 2.f * w4};
#pragma unroll
        for (int m = 0; m < MM; m++)
            g_Whf[((size_t)m * OO + o) * FF + f] = __float2half_rn(p[m]);
    }
}

// ---------------- SpMM: smem-staged edges, HFMA2 dual accumulators ----------------
#define ECHUNK 128

__global__ void __launch_bounds__(256) k_spmm(int stage, int s) {
    __shared__ uint2 sedge[ECHUNK];                   // {col, half2(v)}
    const int n = blockIdx.x;
    const int col = blockIdx.z * 256 + threadIdx.x;   // uint4 index in row [0,512)
    const int srcm = (stage == 0) ? 0 : 1 + 2 * s;
    const int dstm = (stage == 0) ? 1 + 2 * s : 2 + 2 * s;
    const uint4* src = (const uint4*)(g_Xh + (size_t)srcm * NB * ROWLEN) + col;
    uint4* dst = (uint4*)(g_Xh + (size_t)dstm * NB * ROWLEN) + (size_t)n * 512 + col;
    const int e0  = g_off[s * (NB + 1) + n];
    const int end = g_off[s * (NB + 1) + n + 1];
    const float2* ep = g_edges + s * EE;

    __half2 accE[4], accO[4];
    const __half2 z2 = __floats2half2_rn(0.f, 0.f);
#pragma unroll
    for (int j = 0; j < 4; j++) { accE[j] = z2; accO[j] = z2; }

    for (int base = e0; base < end; base += ECHUNK) {
        const int cnt = min(ECHUNK, end - base);
        if (base > e0) __syncthreads();
        if (threadIdx.x < cnt) {
            float2 cv = ep[base + threadIdx.x];
            __half2 vh = __half2half2(__float2half_rn(cv.y));
            sedge[threadIdx.x] = make_uint2((uint32_t)__float_as_int(cv.x),
                                            *(uint32_t*)&vh);
        }
        __syncthreads();

        int i = 0;
        for (; i + 8 <= cnt; i += 8) {
            uint2 se[8];
#pragma unroll
            for (int k = 0; k < 8; k++) se[k] = sedge[i + k];
            uint4 r[8];
#pragma unroll
            for (int k = 0; k < 8; k++)
                r[k] = src[(size_t)se[k].x * 512];
#pragma unroll
            for (int k = 0; k < 8; k++) {
                __half2 vh = *(__half2*)&se[k].y;
                const __half2* h = (const __half2*)&r[k];
                __half2* acc = (k & 1) ? accO : accE;
#pragma unroll
                for (int j = 0; j < 4; j++)
                    acc[j] = __hfma2(vh, h[j], acc[j]);
            }
        }
        for (; i < cnt; i++) {
            uint2 se = sedge[i];
            uint4 r = src[(size_t)se.x * 512];
            __half2 vh = *(__half2*)&se.y;
            const __half2* h = (const __half2*)&r;
#pragma unroll
            for (int j = 0; j < 4; j++)
                accE[j] = __hfma2(vh, h[j], accE[j]);
        }
    }

    uint4 o;
    __half2* po = (__half2*)&o;
#pragma unroll
    for (int j = 0; j < 4; j++) {
        float2 fe = __half22float2(accE[j]);
        float2 fo = __half22float2(accO[j]);
        po[j] = __floats2half2_rn(fe.x + fo.x, fe.y + fo.y);
    }
    *dst = o;
}

// ---------------- GEMM: all fp16 MMA; m=0 A hi/lo x2, m>=1 x1 ----------------
#define BK   32
#define BKP  40
#define TSZ  (128 * BKP)
#define STG3 (3 * TSZ)               // tiles: A(hi) | A(lo) | B
#define GEMM_SMEM (2 * STG3 * 2)     // 61440 B

__device__ __forceinline__ void mma_f16(float* c, const uint32_t* a, const uint32_t* b) {
    asm volatile(
        "mma.sync.aligned.m16n8k16.row.col.f32.f16.f16.f32 "
        "{%0,%1,%2,%3}, {%4,%5,%6,%7}, {%8,%9}, {%0,%1,%2,%3};\n"
        : "+f"(c[0]), "+f"(c[1]), "+f"(c[2]), "+f"(c[3])
        : "r"(a[0]), "r"(a[1]), "r"(a[2]), "r"(a[3]), "r"(b[0]), "r"(b[1]));
}
__device__ __forceinline__ void ldsm_x4(uint32_t* r, uint32_t saddr) {
    asm volatile("ldmatrix.sync.aligned.m8n8.x4.shared.b16 {%0,%1,%2,%3}, [%4];"
                 : "=r"(r[0]), "=r"(r[1]), "=r"(r[2]), "=r"(r[3]) : "r"(saddr));
}

__global__ void __launch_bounds__(256) k_gemm_mma(const float* __restrict__ inputs,
                                                  const float* __restrict__ state,
                                                  const float* __restrict__ biases,
                                                  float* __restrict__ out) {
    extern __shared__ uint16_t smx[];   // [2][Ah|Al|B][128][BKP]
    const uint32_t smem0 = (uint32_t)__cvta_generic_to_shared(smx);

    const int t = threadIdx.x;
    const int wid = t >> 5, lane = t & 31;
    const int qr = lane >> 2, qc = lane & 3;
    const int wm = wid & 1, wn = wid >> 1;

    const int bn0 = blockIdx.x * 128;
    const int n0 = bn0 & (NB - 1);
    const int b  = bn0 >> 12;

    const int ar = t >> 1, ah = t & 1;   // A ldg: row, 16-elem half
    const int bo = t & 127, bp = t >> 7; // B ldg: o row, 16-elem part

    const int aRowOff = (wm * 64 + (lane & 15)) * BKP + ((lane >> 4) << 3);
    const int bRowOff = (wn * 32 + ((lane >> 4) << 3) + (lane & 7)) * BKP + (lane & 8);

    float acc[4][4][4];
#pragma unroll
    for (int i = 0; i < 4; i++)
#pragma unroll
        for (int j = 0; j < 4; j++)
#pragma unroll
            for (int k = 0; k < 4; k++) acc[i][j][k] = 0.f;

    float4 aRegF[4];                 // m=0: fp32 A (from inputs/state)
    uint4  aRegR[2];                 // m>=1: raw fp16 A
    uint4  bReg[2];                  // fp16 W

    auto ldg_tile = [&](int kt) {
        const int m_ = kt >> 2, f0_ = (kt & 3) * BK;
        if (m_ == 0) {
            const int fseg = f0_ + ah * 16;           // {0,16,...,112}
            const float* src = (fseg < DD)
                ? inputs + ((size_t)b * NB + (n0 + ar)) * DD + fseg
                : state  + ((size_t)b * NB + (n0 + ar)) * HH + (fseg - DD);
            const float4* ap = (const float4*)src;
            aRegF[0] = ap[0]; aRegF[1] = ap[1]; aRegF[2] = ap[2]; aRegF[3] = ap[3];
        } else {
            const uint4* apf = (const uint4*)(g_Xh +
                (((size_t)m_ * NB + (n0 + ar)) * BB + b) * FF + f0_ + ah * 16);
            aRegR[0] = apf[0]; aRegR[1] = apf[1];
        }
        const uint4* bf = (const uint4*)(g_Whf + ((size_t)m_ * OO + bo) * FF +
                                         f0_ + bp * 16);
        bReg[0] = bf[0]; bReg[1] = bf[1];
    };

    auto sts_tile = [&](int st, bool isM0) {
        uint16_t* Ah = smx + st * STG3;
        uint16_t* Al = Ah + TSZ;
        uint16_t* Bt = Ah + 2 * TSZ;
        if (isM0) {
            const float* av = (const float*)aRegF;
            uint32_t* AhR = (uint32_t*)(Ah + ar * BKP + ah * 16);
            uint32_t* AlR = (uint32_t*)(Al + ar * BKP + ah * 16);
#pragma unroll
            for (int j = 0; j < 8; j++) {
                float x0 = av[2 * j], x1 = av[2 * j + 1];
                __half h0 = __float2half_rn(x0);
                __half h1 = __float2half_rn(x1);
                __half l0 = __float2half_rn(x0 - __half2float(h0));
                __half l1 = __float2half_rn(x1 - __half2float(h1));
                __half2 hp; hp.x = h0; hp.y = h1;
                __half2 lp; lp.x = l0; lp.y = l1;
                AhR[j] = *(uint32_t*)&hp;
                AlR[j] = *(uint32_t*)&lp;
            }
        } else {
            uint4* Ar = (uint4*)(Ah + ar * BKP + ah * 16);
            Ar[0] = aRegR[0]; Ar[1] = aRegR[1];
        }
        uint4* Br = (uint4*)(Bt + bo * BKP + bp * 16);
        Br[0] = bReg[0]; Br[1] = bReg[1];
    };

    ldg_tile(0);
    sts_tile(0, true);
    __syncthreads();

    for (int kt = 0; kt < 20; kt++) {
        const int st = kt & 1;
        if (kt < 19) ldg_tile(kt + 1);

        const uint32_t baseAh = smem0 + (st * STG3) * 2;
        const uint32_t baseAl = baseAh + TSZ * 2;
        const uint32_t baseB  = baseAh + 2 * TSZ * 2;

        if (kt < 4) {
            // m=0 slab: fp16 hi/lo x2
#pragma unroll
            for (int kk = 0; kk < BK; kk += 16) {
                uint32_t fb[4][2];
#pragma unroll
                for (int p = 0; p < 2; p++) {
                    uint32_t r[4];
                    uint32_t off = (bRowOff + p * 16 * BKP + kk) * 2;
                    ldsm_x4(r, baseB + off);
                    fb[2 * p][0] = r[0]; fb[2 * p][1] = r[1];
                    fb[2 * p + 1][0] = r[2]; fb[2 * p + 1][1] = r[3];
                }
#pragma unroll
                for (int mi = 0; mi < 4; mi++) {
                    uint32_t fah[4], fal[4];
                    uint32_t off = (aRowOff + mi * 16 * BKP + kk) * 2;
                    ldsm_x4(fah, baseAh + off);
                    ldsm_x4(fal, baseAl + off);
#pragma unroll
                    for (int ni = 0; ni < 4; ni++) {
                        mma_f16(acc[mi][ni], fah, fb[ni]);
                        mma_f16(acc[mi][ni], fal, fb[ni]);
                    }
                }
            }
        } else {
            // m>=1 slabs: single fp16 MMA
#pragma unroll
            for (int kk = 0; kk < BK; kk += 16) {
                uint32_t fb[4][2];
#pragma unroll
                for (int p = 0; p < 2; p++) {
                    uint32_t r[4];
                    uint32_t off = (bRowOff + p * 16 * BKP + kk) * 2;
                    ldsm_x4(r, baseB + off);
                    fb[2 * p][0] = r[0]; fb[2 * p][1] = r[1];
                    fb[2 * p + 1][0] = r[2]; fb[2 * p + 1][1] = r[3];
                }
#pragma unroll
                for (int mi = 0; mi < 4; mi++) {
                    uint32_t fa[4];
                    uint32_t off = (aRowOff + mi * 16 * BKP + kk) * 2;
                    ldsm_x4(fa, baseAh + off);
#pragma unroll
                    for (int ni = 0; ni < 4; ni++)
                        mma_f16(acc[mi][ni], fa, fb[ni]);
                }
            }
        }

        if (kt < 19) sts_tile(1 - st, (kt + 1) < 4);
        __syncthreads();
    }

#pragma unroll
    for (int mi = 0; mi < 4; mi++) {
#pragma unroll
        for (int ni = 0; ni < 4; ni++) {
            int col = wn * 32 + ni * 8 + 2 * qc;
            float b0 = biases[col], b1 = biases[col + 1];
            int r0 = bn0 + wm * 64 + mi * 16 + qr;
            float2 v0 = make_float2(acc[mi][ni][0] + b0, acc[mi][ni][1] + b1);
            float2 v1 = make_float2(acc[mi][ni][2] + b0, acc[mi][ni][3] + b1);
            *(float2*)(out + (size_t)r0 * OO + col)       = v0;
            *(float2*)(out + (size_t)(r0 + 8) * OO + col) = v1;
        }
    }
}

// ---------------- launch (serial, 7 launches) ----------------
extern "C" void kernel_launch(void* const* d_in, const int* in_sizes, int n_in,
                              void* d_out, int out_size) {
    const float* inputs = (const float*)d_in[0];
    const float* state  = (const float*)d_in[1];
    const int*   rows   = (const int*)d_in[2];
    const int*   cols   = (const int*)d_in[3];
    const float* vals   = (const float*)d_in[4];
    const float* weight = (const float*)d_in[5];
    const float* biases = (const float*)d_in[6];
    float* out = (float*)d_out;
    (void)in_sizes; (void)n_in; (void)out_size;

    cudaFuncSetAttribute(k_gemm_mma, cudaFuncAttributeMaxDynamicSharedMemorySize,
                         GEMM_SMEM);

    k_csr<<<SS, 1024>>>(rows);
    k_scatter_build<<<SCAT_BLOCKS + BUILD_BLOCKS + WPREP_BLOCKS, 256>>>(
        rows, cols, vals, (const float4*)inputs, (const float4*)state, weight);
    k_spmm<<<dim3(NB, 1, 2), 256>>>(0, 0);     // Y0 = A0 X0   (src slot0, dst slot1)
    k_spmm<<<dim3(NB, 1, 2), 256>>>(0, 1);     // Y1 = A1 X0   (src slot0, dst slot3)
    k_spmm<<<dim3(NB, 1, 2), 256>>>(1, 0);     // Z0 = A0 Y0   (src slot1, dst slot2)
    k_spmm<<<dim3(NB, 1, 2), 256>>>(1, 1);     // Z1 = A1 Y1   (src slot3, dst slot4)
    k_gemm_mma<<<(BB * NB) / 128, 256, GEMM_SMEM>>>(inputs, state, biases, out);
}

// round 17
// speedup vs baseline: 1.3601x; 1.1521x over previous
#include <cuda_runtime.h>
#include <cuda_fp16.h>
#include <cstdint>

// DiffusionGraphConv — GB300 sm_103 (baseline PTX; no tcgen05 in this toolchain)
//   1) k_csr: smem histogram + scan (one kernel, 2 CTAs)
//   2) k_scatter_build: edge scatter || X0h build || weight fold (one launch)
//   3) SpMM: stage0 combined + stage1 split (R13 layout — proven optimum over
//      persistent/grid-stride R15 and 4-way split R16)
//   4) GEMM: uniform single fp16 MMA for ALL slabs (m=0 now from X0h too)

#define NB 4096
#define BB 32
#define DD 64
#define HH 64
#define FF 128
#define EE 65536
#define SS 2
#define MM 5
#define OO 128
#define ROWLEN (BB * FF)

// ---- device scratch ----
__device__ __half g_Xh[(size_t)MM * NB * ROWLEN];      // [X0h,Y0,Z0,Y1,Z1] fp16
__device__ float2 g_edges[SS * EE];
__device__ int    g_off[SS * (NB + 1)];
__device__ int    g_cur[SS * NB];
__device__ __half g_Whf[MM * OO * FF];                 // folded, transposed [m][o][f] fp16

// ---------------- CSR front-end: histogram + scan in one kernel ----------------
__global__ void __launch_bounds__(1024) k_csr(const int* __restrict__ rows) {
    __shared__ int hist[NB];          // 16KB
    __shared__ int wsum[32];
    const int s = blockIdx.x;
    const int t = threadIdx.x;

#pragma unroll
    for (int j = 0; j < 4; j++) hist[t * 4 + j] = 0;
    __syncthreads();

    const int* rp = rows + s * EE;
    for (int i = t; i < EE; i += 1024)
        atomicAdd(&hist[rp[i]], 1);
    __syncthreads();

    int v0 = hist[t * 4 + 0], v1 = hist[t * 4 + 1];
    int v2 = hist[t * 4 + 2], v3 = hist[t * 4 + 3];
    int tot = v0 + v1 + v2 + v3;
    int lane = t & 31, w = t >> 5;
    int x = tot;
#pragma unroll
    for (int d = 1; d < 32; d <<= 1) {
        int y = __shfl_up_sync(0xffffffffu, x, d);
        if (lane >= d) x += y;
    }
    if (lane == 31) wsum[w] = x;
    __syncthreads();
    if (w == 0) {
        int y = wsum[lane];
#pragma unroll
        for (int d = 1; d < 32; d <<= 1) {
            int z = __shfl_up_sync(0xffffffffu, y, d);
            if (lane >= d) y += z;
        }
        wsum[lane] = y;
    }
    __syncthreads();
    int excl = x - tot + (w > 0 ? wsum[w - 1] : 0);
    int ob = s * (NB + 1) + t * 4;
    int cb = s * NB + t * 4;
    g_off[ob + 0] = excl;
    g_off[ob + 1] = excl + v0;
    g_off[ob + 2] = excl + v0 + v1;
    g_off[ob + 3] = excl + v0 + v1 + v2;
    g_cur[cb + 0] = excl;
    g_cur[cb + 1] = excl + v0;
    g_cur[cb + 2] = excl + v0 + v1;
    g_cur[cb + 3] = excl + v0 + v1 + v2;
    if (t == 1023) g_off[s * (NB + 1) + NB] = excl + tot;
}

// ---------------- scatter + X0h build + weight fold (one grid-partitioned launch) ----------------
#define SCAT_BLOCKS ((SS * EE) / 256)                       // 512
#define BUILD_BLOCKS ((NB * BB * 32) / 256)                 // 16384
#define WPREP_BLOCKS ((FF * OO) / 256)                      // 64

__global__ void __launch_bounds__(256) k_scatter_build(
    const int* __restrict__ rows, const int* __restrict__ cols,
    const float* __restrict__ vals,
    const float4* __restrict__ in, const float4* __restrict__ st,
    const float* __restrict__ w) {
    if (blockIdx.x < SCAT_BLOCKS) {
        int i = blockIdx.x * blockDim.x + threadIdx.x;
        int s = i >> 16;
        int r = rows[i];
        int p = atomicAdd(&g_cur[s * NB + r], 1);
        g_edges[s * EE + p] = make_float2(__int_as_float(cols[i]), vals[i]);
    } else if (blockIdx.x < SCAT_BLOCKS + BUILD_BLOCKS) {
        int tid = (blockIdx.x - SCAT_BLOCKS) * blockDim.x + threadIdx.x;
        int q = tid & 31;
        int b = (tid >> 5) & 31;
        int n = tid >> 10;
        float4 v;
        if (q < 16)
            v = in[(size_t)b * (NB * DD / 4) + n * (DD / 4) + q];
        else
            v = st[(size_t)b * (NB * HH / 4) + n * (HH / 4) + (q - 16)];
        size_t off = (size_t)n * ROWLEN + b * FF + q * 4;
        __half2 h0 = __floats2half2_rn(v.x, v.y);
        __half2 h1 = __floats2half2_rn(v.z, v.w);
        uint2 u;
        u.x = *(uint32_t*)&h0;
        u.y = *(uint32_t*)&h1;
        *(uint2*)(g_Xh + off) = u;
    } else {
        int i = (blockIdx.x - SCAT_BLOCKS - BUILD_BLOCKS) * blockDim.x + threadIdx.x;
        int f = i & 127;
        int o = i >> 7;
        float w0 = w[(f * MM + 0) * OO + o];
        float w1 = w[(f * MM + 1) * OO + o];
        float w2 = w[(f * MM + 2) * OO + o];
        float w3 = w[(f * MM + 3) * OO + o];
        float w4 = w[(f * MM + 4) * OO + o];
        float p[5] = {w0 - w2 - w4, w1, 2.f * w2, w3, 2.f * w4};
#pragma unroll
        for (int m = 0; m < MM; m++)
            g_Whf[((size_t)m * OO + o) * FF + f] = __float2half_rn(p[m]);
    }
}

// ---------------- SpMM: smem-staged edges, HFMA2 dual accumulators ----------------
#define ECHUNK 128

__global__ void __launch_bounds__(256) k_spmm(int stage, int sfix) {
    __shared__ uint2 sedge[ECHUNK];                   // {col, half2(v)}
    const int n = blockIdx.x;
    const int s = (sfix < 0) ? (int)blockIdx.y : sfix;
    const int col = blockIdx.z * 256 + threadIdx.x;   // uint4 index in row [0,512)
    const int srcm = (stage == 0) ? 0 : 1 + 2 * s;
    const int dstm = (stage == 0) ? 1 + 2 * s : 2 + 2 * s;
    const uint4* src = (const uint4*)(g_Xh + (size_t)srcm * NB * ROWLEN) + col;
    uint4* dst = (uint4*)(g_Xh + (size_t)dstm * NB * ROWLEN) + (size_t)n * 512 + col;
    const int e0  = g_off[s * (NB + 1) + n];
    const int end = g_off[s * (NB + 1) + n + 1];
    const float2* ep = g_edges + s * EE;

    __half2 accE[4], accO[4];
    const __half2 z2 = __floats2half2_rn(0.f, 0.f);
#pragma unroll
    for (int j = 0; j < 4; j++) { accE[j] = z2; accO[j] = z2; }

    for (int base = e0; base < end; base += ECHUNK) {
        const int cnt = min(ECHUNK, end - base);
        if (base > e0) __syncthreads();
        if (threadIdx.x < cnt) {
            float2 cv = ep[base + threadIdx.x];
            __half2 vh = __half2half2(__float2half_rn(cv.y));
            sedge[threadIdx.x] = make_uint2((uint32_t)__float_as_int(cv.x),
                                            *(uint32_t*)&vh);
        }
        __syncthreads();

        int i = 0;
        for (; i + 8 <= cnt; i += 8) {
            uint2 se[8];
#pragma unroll
            for (int k = 0; k < 8; k++) se[k] = sedge[i + k];
            uint4 r[8];
#pragma unroll
            for (int k = 0; k < 8; k++)
                r[k] = src[(size_t)se[k].x * 512];
#pragma unroll
            for (int k = 0; k < 8; k++) {
                __half2 vh = *(__half2*)&se[k].y;
                const __half2* h = (const __half2*)&r[k];
                __half2* acc = (k & 1) ? accO : accE;
#pragma unroll
                for (int j = 0; j < 4; j++)
                    acc[j] = __hfma2(vh, h[j], acc[j]);
            }
        }
        for (; i < cnt; i++) {
            uint2 se = sedge[i];
            uint4 r = src[(size_t)se.x * 512];
            __half2 vh = *(__half2*)&se.y;
            const __half2* h = (const __half2*)&r;
#pragma unroll
            for (int j = 0; j < 4; j++)
                accE[j] = __hfma2(vh, h[j], accE[j]);
        }
    }

    uint4 o;
    __half2* po = (__half2*)&o;
#pragma unroll
    for (int j = 0; j < 4; j++) {
        float2 fe = __half22float2(accE[j]);
        float2 fo = __half22float2(accO[j]);
        po[j] = __floats2half2_rn(fe.x + fo.x, fe.y + fo.y);
    }
    *dst = o;
}

// ---------------- GEMM: uniform fp16 MMA over all 5 slabs ----------------
#define BK   32
#define BKP  40
#define TSZ  (128 * BKP)
#define STG2 (2 * TSZ)               // tiles: A | B
#define GEMM_SMEM (2 * STG2 * 2)     // 40960 B

__device__ __forceinline__ void mma_f16(float* c, const uint32_t* a, const uint32_t* b) {
    asm volatile(
        "mma.sync.aligned.m16n8k16.row.col.f32.f16.f16.f32 "
        "{%0,%1,%2,%3}, {%4,%5,%6,%7}, {%8,%9}, {%0,%1,%2,%3};\n"
        : "+f"(c[0]), "+f"(c[1]), "+f"(c[2]), "+f"(c[3])
        : "r"(a[0]), "r"(a[1]), "r"(a[2]), "r"(a[3]), "r"(b[0]), "r"(b[1]));
}
__device__ __forceinline__ void ldsm_x4(uint32_t* r, uint32_t saddr) {
    asm volatile("ldmatrix.sync.aligned.m8n8.x4.shared.b16 {%0,%1,%2,%3}, [%4];"
                 : "=r"(r[0]), "=r"(r[1]), "=r"(r[2]), "=r"(r[3]) : "r"(saddr));
}

__global__ void __launch_bounds__(256) k_gemm_mma(const float* __restrict__ biases,
                                                  float* __restrict__ out) {
    extern __shared__ uint16_t smx[];   // [2][A|B][128][BKP]
    const uint32_t smem0 = (uint32_t)__cvta_generic_to_shared(smx);

    const int t = threadIdx.x;
    const int wid = t >> 5, lane = t & 31;
    const int qr = lane >> 2, qc = lane & 3;
    const int wm = wid & 1, wn = wid >> 1;

    const int bn0 = blockIdx.x * 128;
    const int n0 = bn0 & (NB - 1);
    const int b  = bn0 >> 12;

    const int ar = t >> 1, ah = t & 1;   // A ldg: row, 16-elem half
    const int bo = t & 127, bp = t >> 7; // B ldg: o row, 16-elem part

    const int aRowOff = (wm * 64 + (lane & 15)) * BKP + ((lane >> 4) << 3);
    const int bRowOff = (wn * 32 + ((lane >> 4) << 3) + (lane & 7)) * BKP + (lane & 8);

    float acc[4][4][4];
#pragma unroll
    for (int i = 0; i < 4; i++)
#pragma unroll
        for (int j = 0; j < 4; j++)
#pragma unroll
            for (int k = 0; k < 4; k++) acc[i][j][k] = 0.f;

    uint4 aReg[2], bReg[2];

    auto ldg_tile = [&](int kt) {
        const int m_ = kt >> 2, f0_ = (kt & 3) * BK;
        const uint4* ap = (const uint4*)(g_Xh +
            (((size_t)m_ * NB + (n0 + ar)) * BB + b) * FF + f0_ + ah * 16);
        aReg[0] = ap[0]; aReg[1] = ap[1];
        const uint4* bf = (const uint4*)(g_Whf + ((size_t)m_ * OO + bo) * FF +
                                         f0_ + bp * 16);
        bReg[0] = bf[0]; bReg[1] = bf[1];
    };

    auto sts_tile = [&](int st) {
        uint16_t* At = smx + st * STG2;
        uint16_t* Bt = At + TSZ;
        uint4* Ar = (uint4*)(At + ar * BKP + ah * 16);
        Ar[0] = aReg[0]; Ar[1] = aReg[1];
        uint4* Br = (uint4*)(Bt + bo * BKP + bp * 16);
        Br[0] = bReg[0]; Br[1] = bReg[1];
    };

    ldg_tile(0);
    sts_tile(0);
    __syncthreads();

    for (int kt = 0; kt < 20; kt++) {
        const int st = kt & 1;
        if (kt < 19) ldg_tile(kt + 1);

        const uint32_t baseA = smem0 + (st * STG2) * 2;
        const uint32_t baseB = baseA + TSZ * 2;

#pragma unroll
        for (int kk = 0; kk < BK; kk += 16) {
            uint32_t fb[4][2];
#pragma unroll
            for (int p = 0; p < 2; p++) {
                uint32_t r[4];
                uint32_t off = (bRowOff + p * 16 * BKP + kk) * 2;
                ldsm_x4(r, baseB + off);
                fb[2 * p][0] = r[0]; fb[2 * p][1] = r[1];
                fb[2 * p + 1][0] = r[2]; fb[2 * p + 1][1] = r[3];
            }
#pragma unroll
            for (int mi = 0; mi < 4; mi++) {
                uint32_t fa[4];
                uint32_t off = (aRowOff + mi * 16 * BKP + kk) * 2;
                ldsm_x4(fa, baseA + off);
#pragma unroll
                for (int ni = 0; ni < 4; ni++)
                    mma_f16(acc[mi][ni], fa, fb[ni]);
            }
        }

        if (kt < 19) sts_tile(1 - st);
        __syncthreads();
    }

#pragma unroll
    for (int mi = 0; mi < 4; mi++) {
#pragma unroll
        for (int ni = 0; ni < 4; ni++) {
            int col = wn * 32 + ni * 8 + 2 * qc;
            float b0 = biases[col], b1 = biases[col + 1];
            int r0 = bn0 + wm * 64 + mi * 16 + qr;
            float2 v0 = make_float2(acc[mi][ni][0] + b0, acc[mi][ni][1] + b1);
            float2 v1 = make_float2(acc[mi][ni][2] + b0, acc[mi][ni][3] + b1);
            *(float2*)(out + (size_t)r0 * OO + col)       = v0;
            *(float2*)(out + (size_t)(r0 + 8) * OO + col) = v1;
        }
    }
}

// ---------------- launch (serial, 6 launches — R13 layout) ----------------
extern "C" void kernel_launch(void* const* d_in, const int* in_sizes, int n_in,
                              void* d_out, int out_size) {
    const float* inputs = (const float*)d_in[0];
    const float* state  = (const float*)d_in[1];
    const int*   rows   = (const int*)d_in[2];
    const int*   cols   = (const int*)d_in[3];
    const float* vals   = (const float*)d_in[4];
    const float* weight = (const float*)d_in[5];
    const float* biases = (const float*)d_in[6];
    float* out = (float*)d_out;
    (void)in_sizes; (void)n_in; (void)out_size;

    cudaFuncSetAttribute(k_gemm_mma, cudaFuncAttributeMaxDynamicSharedMemorySize,
                         GEMM_SMEM);

    k_csr<<<SS, 1024>>>(rows);
    k_scatter_build<<<SCAT_BLOCKS + BUILD_BLOCKS + WPREP_BLOCKS, 256>>>(
        rows, cols, vals, (const float4*)inputs, (const float4*)state, weight);
    k_spmm<<<dim3(NB, SS, 2), 256>>>(0, -1);   // stage0: both supports (shared src)
    k_spmm<<<dim3(NB, 1, 2), 256>>>(1, 0);     // stage1 s=0
    k_spmm<<<dim3(NB, 1, 2), 256>>>(1, 1);     // stage1 s=1
    k_gemm_mma<<<(BB * NB) / 128, 256, GEMM_SMEM>>>(biases, out);
}